// round 6
// baseline (speedup 1.0000x reference)
#include <cuda_runtime.h>

typedef unsigned long long u64;

#define N_NODES 20000
#define N_EDGES 320000
#define NF 128
#define NH 64
#define NG 16
#define NL 5
#define EPS 1e-5f
#define NB 296
#define NT 256
#define GT (NB * NT)          // 75776 threads
#define NWARPS (GT / 32)      // 2368
#define SMEM_BYTES ((NF * NH + NH * NF + NH + NF) * 4)   // 66304

// ---------------- scratch ---------------------------------------------------
__device__ float4 g_h4[N_NODES * NF / 4];
__device__ float4 g_m4[N_NODES * NF / 4];
__device__ float4 g_g4[N_NODES * NF / 4];
__device__ float  g_gsum[NG * NF];
__device__ float  g_vsum[NG * NF];
__device__ float  g_psum[NG * NF];
__device__ float  g_A[NG * NF];
__device__ float  g_B[NG * NF];
__device__ float  g_cnt[NG];
__device__ int    g_src[N_EDGES];
__device__ int    g_dst[N_EDGES];
__device__ int    g_batch[N_NODES];
__device__ int    g_deg[N_NODES];
__device__ int    g_roff[N_NODES + 1];
__device__ int    g_cur[N_NODES];
__device__ int    g_eidx[N_EDGES];
__device__ int    g_bsum[NB];
__device__ int    g_boff[NB];
__device__ int    g_gstart[NG + 1];
__device__ unsigned g_bar_arrive = 0;
__device__ unsigned g_bar_gen = 0;

// ---------------- helpers ----------------------------------------------------
__device__ __forceinline__ u64 pack2(float lo, float hi) {
    u64 r; asm("mov.b64 %0,{%1,%2};" : "=l"(r) : "f"(lo), "f"(hi)); return r;
}
__device__ __forceinline__ float2 unpack2(u64 v) {
    float2 f; asm("mov.b64 {%0,%1},%2;" : "=f"(f.x), "=f"(f.y) : "l"(v)); return f;
}
__device__ __forceinline__ void fma2(u64& d, u64 a, u64 b) {
    asm("fma.rn.f32x2 %0,%1,%2,%0;" : "+l"(d) : "l"(a), "l"(b));
}
__device__ __forceinline__ void red_v4(float* p, float4 v) {
    asm volatile("red.global.add.v4.f32 [%0],{%1,%2,%3,%4};"
                 :: "l"(p), "f"(v.x), "f"(v.y), "f"(v.z), "f"(v.w) : "memory");
}

// generation-counting software grid barrier (all NB blocks resident)
__device__ __forceinline__ void grid_barrier() {
    __syncthreads();
    if (threadIdx.x == 0) {
        __threadfence();                       // release my block's writes
        unsigned gen = *(volatile unsigned*)&g_bar_gen;
        if (atomicAdd(&g_bar_arrive, 1u) == NB - 1) {
            g_bar_arrive = 0;
            __threadfence();
            atomicAdd(&g_bar_gen, 1u);         // release
        } else {
            while (*(volatile unsigned*)&g_bar_gen == gen) __nanosleep(64);
        }
        __threadfence();                       // acquire (invalidates L1)
    }
    __syncthreads();
}

// ---------------- the persistent kernel --------------------------------------
__global__ void __launch_bounds__(NT, 2)
persist_kernel(const float* __restrict__ x,
               const int* __restrict__ ei, const int* __restrict__ braw,
               const float* __restrict__ W1a, const float* __restrict__ b1a,
               const float* __restrict__ W2a, const float* __restrict__ b2a,
               const float* __restrict__ gnw, const float* __restrict__ gnb,
               const float* __restrict__ gns,
               const float* __restrict__ linw, const float* __restrict__ linb,
               float* __restrict__ out)
{
    extern __shared__ float sm[];
    float* sW1 = sm;                    // [128][64]
    float* sW2 = sm + NF * NH;          // [64][128]
    float* sb1 = sW2 + NH * NF;
    float* sb2 = sb1 + NH;
    int*   sc  = (int*)sm;              // scan scratch (pre-layer phases only)
    __shared__ int sblk;

    const int tid  = threadIdx.x;
    const int bid  = blockIdx.x;
    const int gtid = bid * NT + tid;
    const int lane = tid & 31;

    // ===== phase 0: idx-width detect + convert + zero accumulators ==========
    int okp = 1;
    if (tid < 128) okp = (ei[2 * tid + 1] == 0);
    const int is64 = __syncthreads_and(okp);

    const int TOT0 = 2 * N_EDGES + 2 * N_NODES + 3 * NG * NF;
    for (int idx = gtid; idx < TOT0; idx += GT) {
        if (idx < N_EDGES) {
            g_src[idx] = is64 ? ei[2 * idx] : ei[idx];
        } else if (idx < 2 * N_EDGES) {
            int e = idx - N_EDGES;
            g_dst[e] = is64 ? ei[2 * N_EDGES + 2 * e] : ei[N_EDGES + e];
        } else if (idx < 2 * N_EDGES + N_NODES) {
            int n = idx - 2 * N_EDGES;
            g_batch[n] = is64 ? braw[2 * n] : braw[n];
        } else if (idx < 2 * N_EDGES + 2 * N_NODES) {
            g_deg[idx - 2 * N_EDGES - N_NODES] = 0;
        } else {
            int r = idx - 2 * N_EDGES - 2 * N_NODES;
            if (r < NG * NF) g_gsum[r] = 0.f;
            else if (r < 2 * NG * NF) g_vsum[r - NG * NF] = 0.f;
            else g_psum[r - 2 * NG * NF] = 0.f;
        }
    }
    grid_barrier();

    // ===== phase 1: degree histogram =========================================
    for (int e = gtid; e < N_EDGES; e += GT) atomicAdd(&g_deg[g_dst[e]], 1);
    grid_barrier();

    // ===== phase 2: per-block degree partials + graph-start search ===========
    const int NCH = (N_NODES + NB - 1) / NB;    // 68
    {
        int n0 = bid * NCH, n1 = min(n0 + NCH, N_NODES);
        int s = 0;
        for (int n = n0 + tid; n < n1; n += NT) s += g_deg[n];
        #pragma unroll
        for (int o = 16; o; o >>= 1) s += __shfl_xor_sync(0xffffffffu, s, o);
        if (tid == 0) sblk = 0;
        __syncthreads();
        if (lane == 0) atomicAdd(&sblk, s);
        __syncthreads();
        if (tid == 0) g_bsum[bid] = sblk;
        if (bid == 0 && tid <= NG) {
            int lo = 0, hi = N_NODES;
            while (lo < hi) {
                int mid = (lo + hi) >> 1;
                if (g_batch[mid] < tid) lo = mid + 1; else hi = mid;
            }
            g_gstart[tid] = lo;
        }
    }
    grid_barrier();

    // ===== phase 3: block 0 scans the 296 partials (Hillis-Steele) ==========
    if (bid == 0) {
        int i0 = tid, i1 = tid + 256;
        int o0 = (i0 < NB) ? g_bsum[i0] : 0;
        int o1 = (i1 < NB) ? g_bsum[i1] : 0;
        sc[i0] = o0; sc[i1] = o1;
        __syncthreads();
        for (int off = 1; off < 512; off <<= 1) {
            int a0 = (i0 >= off) ? sc[i0 - off] : 0;
            int a1 = (i1 >= off) ? sc[i1 - off] : 0;
            __syncthreads();
            sc[i0] += a0; sc[i1] += a1;
            __syncthreads();
        }
        if (i0 < NB) g_boff[i0] = sc[i0] - o0;
        if (i1 < NB) g_boff[i1] = sc[i1] - o1;
        if (tid < NG)
            g_cnt[tid] = fmaxf((float)(g_gstart[tid + 1] - g_gstart[tid]), 1.f);
        if (tid == 0) g_roff[N_NODES] = N_EDGES;
    }
    grid_barrier();

    // ===== phase 4: per-block local CSR offsets ==============================
    {
        int n0 = bid * NCH, n1 = min(n0 + NCH, N_NODES);
        int cnt = n1 - n0;
        for (int i = tid; i < cnt; i += NT) sc[i] = g_deg[n0 + i];
        __syncthreads();
        if (tid == 0 && cnt > 0) {
            int run = g_boff[bid];
            for (int i = 0; i < cnt; i++) {
                g_roff[n0 + i] = run;
                g_cur[n0 + i] = run;
                run += sc[i];
            }
        }
        __syncthreads();
    }
    grid_barrier();

    // ===== phase 5: CSR fill =================================================
    for (int e = gtid; e < N_EDGES; e += GT) {
        int d = g_dst[e];
        int p = atomicAdd(&g_cur[d], 1);
        g_eidx[p] = g_src[e];
    }
    grid_barrier();

    // ===== layer loop ========================================================
    const int pairi = gtid >> 1;
    const int half  = gtid & 1;
    const int c0    = half * 64;
    const int j0    = half * 32;
    const int wid   = gtid >> 5;

    for (int l = 0; l < NL; l++) {
        // ---- load weights into smem ----
        {
            const float4* w1s = (const float4*)(W1a + l * NF * NH);
            const float4* w2s = (const float4*)(W2a + l * NF * NH);
            for (int i = tid; i < NF * NH / 4; i += NT) {
                ((float4*)sW1)[i] = w1s[i];
                ((float4*)sW2)[i] = w2s[i];
            }
            if (tid < NH) sb1[tid] = b1a[l * NH + tid];
            if (tid < NF) sb2[tid] = b2a[l * NF + tid];
            __syncthreads();
        }
        const int mode = (l == 0) ? 0 : ((l == 1) ? 1 : 2);

        // ---- MLP (finalize prev layer fused): 2 threads/node ----
        {
            int n = pairi;
            bool act = (n < N_NODES);
            int nsafe = act ? n : 0;
            const float4* grow = (const float4*)((const float*)g_g4 + nsafe * NF + c0);
            const float4* hrow = (const float4*)((const float*)g_h4 + nsafe * NF + c0);
            const float4* xrow = (const float4*)(x + nsafe * NF + c0);
            int b = act ? g_batch[n] : 0;
            const float4* Arow = (const float4*)(g_A + b * NF + c0);
            const float4* Brow = (const float4*)(g_B + b * NF + c0);
            float4* hout = (float4*)((float*)g_h4 + nsafe * NF + c0);

            u64 hid2[16];
            #pragma unroll
            for (int q = 0; q < 16; q++) hid2[q] = 0ull;

            #pragma unroll 2
            for (int i = 0; i < 16; i++) {
                float4 h;
                if (mode == 0) {
                    h = xrow[i];
                } else {
                    float4 gv = grow[i], Av = Arow[i], Bv = Brow[i];
                    h.x = fmaxf(fmaf(Av.x, gv.x, Bv.x), 0.f);
                    h.y = fmaxf(fmaf(Av.y, gv.y, Bv.y), 0.f);
                    h.z = fmaxf(fmaf(Av.z, gv.z, Bv.z), 0.f);
                    h.w = fmaxf(fmaf(Av.w, gv.w, Bv.w), 0.f);
                    if (mode == 2) {
                        float4 ho = hrow[i];
                        h.x += ho.x; h.y += ho.y; h.z += ho.z; h.w += ho.w;
                    }
                    if (act) hout[i] = h;
                }
                // own k-pass: k = c0 + 4i + kk, hidden j in [j0, j0+32)
                float hk[4] = {h.x, h.y, h.z, h.w};
                #pragma unroll
                for (int kk = 0; kk < 4; kk++) {
                    u64 pk = pack2(hk[kk], hk[kk]);
                    const ulonglong2* wr =
                        (const ulonglong2*)(sW1 + (c0 + 4 * i + kk) * NH + j0);
                    #pragma unroll
                    for (int q8 = 0; q8 < 8; q8++) {
                        ulonglong2 w = wr[q8];
                        fma2(hid2[2 * q8], pk, w.x);
                        fma2(hid2[2 * q8 + 1], pk, w.y);
                    }
                }
                // partner k-pass: k = (c0^64) + 4i + kk (h via shfl)
                float ok4[4];
                ok4[0] = __shfl_xor_sync(0xffffffffu, h.x, 1);
                ok4[1] = __shfl_xor_sync(0xffffffffu, h.y, 1);
                ok4[2] = __shfl_xor_sync(0xffffffffu, h.z, 1);
                ok4[3] = __shfl_xor_sync(0xffffffffu, h.w, 1);
                #pragma unroll
                for (int kk = 0; kk < 4; kk++) {
                    u64 pk = pack2(ok4[kk], ok4[kk]);
                    const ulonglong2* wr =
                        (const ulonglong2*)(sW1 + ((c0 ^ 64) + 4 * i + kk) * NH + j0);
                    #pragma unroll
                    for (int q8 = 0; q8 < 8; q8++) {
                        ulonglong2 w = wr[q8];
                        fma2(hid2[2 * q8], pk, w.x);
                        fma2(hid2[2 * q8 + 1], pk, w.y);
                    }
                }
            }

            // gemm2: outputs c in [c0, c0+64); hidden split across pair
            u64 acc2[32];
            const ulonglong2* bb2 = (const ulonglong2*)(sb2 + c0);
            #pragma unroll
            for (int q8 = 0; q8 < 16; q8++) {
                ulonglong2 v = bb2[q8];
                acc2[2 * q8] = v.x; acc2[2 * q8 + 1] = v.y;
            }
            #pragma unroll
            for (int q = 0; q < 16; q++) {
                float2 f = unpack2(hid2[q]);
                float h0 = fmaxf(f.x + sb1[j0 + 2 * q], 0.f);
                float h1 = fmaxf(f.y + sb1[j0 + 2 * q + 1], 0.f);
                float p0 = __shfl_xor_sync(0xffffffffu, h0, 1);
                float p1 = __shfl_xor_sync(0xffffffffu, h1, 1);
                u64 ph0 = pack2(h0, h0), ph1 = pack2(h1, h1);
                u64 pp0 = pack2(p0, p0), pp1 = pack2(p1, p1);
                const ulonglong2* wa = (const ulonglong2*)(sW2 + (j0 + 2 * q) * NF + c0);
                const ulonglong2* wb = (const ulonglong2*)(sW2 + (j0 + 2 * q + 1) * NF + c0);
                const ulonglong2* wc = (const ulonglong2*)(sW2 + ((j0 ^ 32) + 2 * q) * NF + c0);
                const ulonglong2* wd = (const ulonglong2*)(sW2 + ((j0 ^ 32) + 2 * q + 1) * NF + c0);
                #pragma unroll
                for (int q8 = 0; q8 < 16; q8++) {
                    ulonglong2 A_ = wa[q8];
                    fma2(acc2[2 * q8], ph0, A_.x); fma2(acc2[2 * q8 + 1], ph0, A_.y);
                    ulonglong2 B_ = wb[q8];
                    fma2(acc2[2 * q8], ph1, B_.x); fma2(acc2[2 * q8 + 1], ph1, B_.y);
                    ulonglong2 C_ = wc[q8];
                    fma2(acc2[2 * q8], pp0, C_.x); fma2(acc2[2 * q8 + 1], pp0, C_.y);
                    ulonglong2 D_ = wd[q8];
                    fma2(acc2[2 * q8], pp1, D_.x); fma2(acc2[2 * q8 + 1], pp1, D_.y);
                }
            }
            if (act) {
                ulonglong2* mo = (ulonglong2*)((float*)g_m4 + n * NF + c0);
                #pragma unroll
                for (int q8 = 0; q8 < 16; q8++) {
                    ulonglong2 v; v.x = acc2[2 * q8]; v.y = acc2[2 * q8 + 1];
                    mo[q8] = v;
                }
            }
        }
        grid_barrier();

        // ---- gather (CSR) + fused segmented gsum/vsum ----
        {
            const int CH2 = (N_NODES + NWARPS - 1) / NWARPS;   // 9
            int n0 = wid * CH2;
            if (n0 < N_NODES) {
                int n1 = min(n0 + CH2, N_NODES);
                int cur = g_batch[n0];
                float4 seg = make_float4(0.f, 0.f, 0.f, 0.f);
                float4 seg2 = make_float4(0.f, 0.f, 0.f, 0.f);
                for (int n = n0; n < n1; n++) {
                    int bb = g_batch[n];
                    if (bb != cur) {
                        red_v4(&g_gsum[cur * NF + lane * 4], seg);
                        red_v4(&g_vsum[cur * NF + lane * 4], seg2);
                        seg = make_float4(0.f, 0.f, 0.f, 0.f);
                        seg2 = make_float4(0.f, 0.f, 0.f, 0.f);
                        cur = bb;
                    }
                    float4 a0 = g_m4[n * 32 + lane];    // self loop
                    float4 a1 = make_float4(0.f, 0.f, 0.f, 0.f), a2 = a1, a3 = a1;
                    int r0 = g_roff[n], r1 = g_roff[n + 1];
                    for (int base = r0; base < r1; base += 32) {
                        int cnt = min(32, r1 - base);
                        int s = (base + lane < r1) ? g_eidx[base + lane] : 0;
                        int j = 0;
                        for (; j + 4 <= cnt; j += 4) {
                            int s0 = __shfl_sync(0xffffffffu, s, j);
                            int s1 = __shfl_sync(0xffffffffu, s, j + 1);
                            int s2 = __shfl_sync(0xffffffffu, s, j + 2);
                            int s3 = __shfl_sync(0xffffffffu, s, j + 3);
                            float4 v0 = g_m4[s0 * 32 + lane];
                            float4 v1 = g_m4[s1 * 32 + lane];
                            float4 v2 = g_m4[s2 * 32 + lane];
                            float4 v3 = g_m4[s3 * 32 + lane];
                            a0.x += v0.x; a0.y += v0.y; a0.z += v0.z; a0.w += v0.w;
                            a1.x += v1.x; a1.y += v1.y; a1.z += v1.z; a1.w += v1.w;
                            a2.x += v2.x; a2.y += v2.y; a2.z += v2.z; a2.w += v2.w;
                            a3.x += v3.x; a3.y += v3.y; a3.z += v3.z; a3.w += v3.w;
                        }
                        for (; j < cnt; j++) {
                            int sj = __shfl_sync(0xffffffffu, s, j);
                            float4 v = g_m4[sj * 32 + lane];
                            a0.x += v.x; a0.y += v.y; a0.z += v.z; a0.w += v.w;
                        }
                    }
                    a0.x += a1.x + a2.x + a3.x;
                    a0.y += a1.y + a2.y + a3.y;
                    a0.z += a1.z + a2.z + a3.z;
                    a0.w += a1.w + a2.w + a3.w;
                    g_g4[n * 32 + lane] = a0;
                    seg.x += a0.x; seg.y += a0.y; seg.z += a0.z; seg.w += a0.w;
                    seg2.x += a0.x * a0.x; seg2.y += a0.y * a0.y;
                    seg2.z += a0.z * a0.z; seg2.w += a0.w * a0.w;
                }
                red_v4(&g_gsum[cur * NF + lane * 4], seg);
                red_v4(&g_vsum[cur * NF + lane * 4], seg2);
            }
        }
        grid_barrier();

        // ---- stats: A,B per (graph, feature); re-zero accumulators ----
        if (gtid < NG * NF) {
            int c = gtid & (NF - 1);
            int i = gtid;
            int g = gtid >> 7;
            float cg = g_cnt[g];
            float mean = g_gsum[i] / cg;
            float E2 = g_vsum[i] / cg;
            float a = gns[l * NF + c];
            float var = E2 - 2.f * a * mean * mean + a * a * mean * mean;
            float inv = rsqrtf(var + EPS);
            float A = gnw[l * NF + c] * inv;
            g_A[i] = A;
            g_B[i] = gnb[l * NF + c] - A * a * mean;
            g_gsum[i] = 0.f;
            g_vsum[i] = 0.f;
        }
        grid_barrier();
    }

    // ===== final: finalize(last layer) + mean-pool accumulation =============
    {
        int n = pairi;
        bool act = (n < N_NODES);
        int nsafe = act ? n : 0;
        int b = act ? g_batch[n] : 0;
        const float4* grow = (const float4*)((const float*)g_g4 + nsafe * NF + c0);
        const float4* hrow = (const float4*)((const float*)g_h4 + nsafe * NF + c0);
        const float4* Arow = (const float4*)(g_A + b * NF + c0);
        const float4* Brow = (const float4*)(g_B + b * NF + c0);

        float4 hv[16];
        #pragma unroll
        for (int i = 0; i < 16; i++) {
            if (act) {
                float4 gv = grow[i], Av = Arow[i], Bv = Brow[i], ho = hrow[i];
                hv[i].x = fmaxf(fmaf(Av.x, gv.x, Bv.x), 0.f) + ho.x;
                hv[i].y = fmaxf(fmaf(Av.y, gv.y, Bv.y), 0.f) + ho.y;
                hv[i].z = fmaxf(fmaf(Av.z, gv.z, Bv.z), 0.f) + ho.z;
                hv[i].w = fmaxf(fmaf(Av.w, gv.w, Bv.w), 0.f) + ho.w;
            } else {
                hv[i] = make_float4(0.f, 0.f, 0.f, 0.f);
            }
        }
        int b0 = __shfl_sync(0xffffffffu, b, 0);
        bool same = __all_sync(0xffffffffu, (!act) || b == b0);
        if (same) {
            #pragma unroll
            for (int off = 2; off < 32; off <<= 1) {
                #pragma unroll
                for (int i = 0; i < 16; i++) {
                    hv[i].x += __shfl_xor_sync(0xffffffffu, hv[i].x, off);
                    hv[i].y += __shfl_xor_sync(0xffffffffu, hv[i].y, off);
                    hv[i].z += __shfl_xor_sync(0xffffffffu, hv[i].z, off);
                    hv[i].w += __shfl_xor_sync(0xffffffffu, hv[i].w, off);
                }
            }
            if (lane < 2) {
                #pragma unroll
                for (int i = 0; i < 16; i++)
                    red_v4(&g_psum[b0 * NF + c0 + 4 * i], hv[i]);
            }
        } else if (act) {
            #pragma unroll
            for (int i = 0; i < 16; i++)
                red_v4(&g_psum[b * NF + c0 + 4 * i], hv[i]);
        }
    }
    grid_barrier();

    // ===== head ==============================================================
    if (gtid < NG * 32) {
        int g = gtid >> 5;
        float v = 0.f;
        for (int c = lane; c < NF; c += 32) v += g_psum[g * NF + c] * linw[c];
        #pragma unroll
        for (int off = 16; off > 0; off >>= 1)
            v += __shfl_down_sync(0xffffffffu, v, off);
        if (lane == 0) out[g] = v / g_cnt[g] + linb[0];
    }
}

// ---------------- launcher --------------------------------------------------
extern "C" void kernel_launch(void* const* d_in, const int* in_sizes, int n_in,
                              void* d_out, int out_size) {
    const float* x    = (const float*)d_in[0];
    const int* ei_raw = (const int*)d_in[1];
    const int* b_raw  = (const int*)d_in[2];
    const float* W1   = (const float*)d_in[3];
    const float* b1   = (const float*)d_in[4];
    const float* W2   = (const float*)d_in[5];
    const float* b2   = (const float*)d_in[6];
    const float* gnw  = (const float*)d_in[7];
    const float* gnb  = (const float*)d_in[8];
    const float* gns  = (const float*)d_in[9];
    const float* linw = (const float*)d_in[10];
    const float* linb = (const float*)d_in[11];
    float* out = (float*)d_out;

    cudaFuncSetAttribute(persist_kernel,
                         cudaFuncAttributeMaxDynamicSharedMemorySize, SMEM_BYTES);

    persist_kernel<<<NB, NT, SMEM_BYTES>>>(
        x, ei_raw, b_raw, W1, b1, W2, b2, gnw, gnb, gns, linw, linb, out);
}